// round 17
// baseline (speedup 1.0000x reference)
#include <cuda_runtime.h>
#include <cuda_bf16.h>
#include <math.h>

#define BB 8
#define TT 1024
#define DD 1024
#define HH 16
#define AD 64
#define BT (BB*TT)      /* 8192 */
#define HA (HH*AD)      /* 1024 */
#define NEDGE 262144
#define BIASDIM 32
#define FBIG 3.402823466e+38f
#define LDSW 12         /* smem row stride in words (48 B) — conflict-free for LDSM */

// ---------------- scratch (no allocations allowed) ----------------
__device__ float g_q[BT*HA];
__device__ float g_k[BT*HA];
__device__ float g_v[BT*HA];
__device__ float g_ctx[BT*HA];
__device__ float g_ksum[BT*HH];        // [bt][h]
__device__ float g_bs[BB*TT*TT];
__device__ int   g_winner[BB*TT*TT];
__device__ float g_alpha[(size_t)BB*HH*TT*TT];
__device__ float2 g_rowstat[BB*HH*TT];  // (rowmax, 1/sum)
__device__ float g_proj[BIASDIM];
__device__ int   g_is64;

// ---------------- bf16 split helpers ----------------
__device__ __forceinline__ unsigned pack2bf(float x0, float x1, float& r0, float& r1) {
    __nv_bfloat16 b0 = __float2bfloat16_rn(x0), b1 = __float2bfloat16_rn(x1);
    r0 = x0 - __bfloat162float(b0);
    r1 = x1 - __bfloat162float(b1);
    return ((unsigned)__bfloat16_as_ushort(b1) << 16) | (unsigned)__bfloat16_as_ushort(b0);
}
__device__ __forceinline__ unsigned pack2bf_o(float x0, float x1) {
    unsigned r; asm("cvt.rn.bf16x2.f32 %0, %1, %2;" : "=r"(r) : "f"(x1), "f"(x0)); return r;
}
__device__ __forceinline__ void mma_bf16(float (&d)[4], const unsigned (&a)[4],
                                         unsigned b0, unsigned b1) {
    asm("mma.sync.aligned.m16n8k16.row.col.f32.bf16.bf16.f32 "
        "{%0,%1,%2,%3}, {%4,%5,%6,%7}, {%8,%9}, {%0,%1,%2,%3};"
        : "+f"(d[0]), "+f"(d[1]), "+f"(d[2]), "+f"(d[3])
        : "r"(a[0]), "r"(a[1]), "r"(a[2]), "r"(a[3]), "r"(b0), "r"(b1));
}
__device__ __forceinline__ void ldsm_x4(unsigned (&r)[4], unsigned addr) {
    asm volatile("ldmatrix.sync.aligned.m8n8.x4.shared.b16 {%0,%1,%2,%3}, [%4];"
        : "=r"(r[0]), "=r"(r[1]), "=r"(r[2]), "=r"(r[3]) : "r"(addr));
}
__device__ __forceinline__ unsigned saddr(const void* p) {
    return (unsigned)__cvta_generic_to_shared(p);
}

// ---------------- fast exp (FMA-only, for x <= 0) ----------------
__device__ __forceinline__ float fexp(float x) {
    float y = fmaxf(x * 1.4426950408889634f, -126.0f);
    int   i = __float2int_rn(y);
    float f = y - (float)i;
    float p = 1.5403530e-4f;
    p = fmaf(p, f, 1.3333558e-3f);
    p = fmaf(p, f, 9.6181291e-3f);
    p = fmaf(p, f, 5.5504109e-2f);
    p = fmaf(p, f, 2.4022651e-1f);
    p = fmaf(p, f, 6.9314718e-1f);
    p = fmaf(p, f, 1.0f);
    return p * __int_as_float((i + 127) << 23);
}

// ---------------- dtype detector for attention_bias ----------------
__global__ void detect_kernel(const int* __restrict__ ab32) {
    int ok = 1;
    #pragma unroll
    for (int i = 0; i < 64; i++) ok &= (ab32[2 * i + 1] == 0);
    g_is64 = ok;
}

// ---------------- proj[et] = bias_embs[et] . bias_scalar ----------------
__global__ void proj_kernel(const float* __restrict__ embs, const float* __restrict__ scal) {
    int et = threadIdx.x;
    if (et >= BIASDIM) return;
    float s = 0.f;
    #pragma unroll
    for (int a = 0; a < AD; a++) s += embs[et * AD + a] * scal[a];
    g_proj[et] = s;
}

// ---------------- BF16 GEMM, ldmatrix fragments: C[M,N] = A[M,K] @ B[K,N] ------
// which_a: 0=ext A, 1=g_ctx.  which_c: 0=g_q, 1=g_k, 2=g_v, 3=ext C.
__global__ __launch_bounds__(256, 2)
void bf16_gemm_kernel(const float* __restrict__ Aext, const float* __restrict__ Bm,
                      float* __restrict__ Cext, int which_a, int which_c,
                      int M, int N, int K) {
    const float* A = (which_a == 1) ? g_ctx : Aext;
    float* C = (which_c == 0) ? g_q : (which_c == 1) ? g_k : (which_c == 2) ? g_v : Cext;
    __shared__ unsigned Ah[128 * LDSW], Al[128 * LDSW];   // [m][kpair words]
    __shared__ unsigned Bh[128 * LDSW], Bl[128 * LDSW];   // [n][kpair words]
    const int tid = threadIdx.x;
    const int wid = tid >> 5, lane = tid & 31;
    const int g = lane >> 2, tq = lane & 3;
    const int r8 = lane & 7, quad = lane >> 3;
    const int warp_m = wid >> 1, warp_n = wid & 1;
    const int m0 = blockIdx.y * 128, n0 = blockIdx.x * 128;

    // loop-invariant ldmatrix addresses
    unsigned adrA[2][2], adrB[2][4];   // [hi/lo][mf], [hi/lo][j]
    {
        int arow = warp_m * 32 + (quad & 1) * 8 + r8;
        int aoff = (quad >> 1) * 16;
        adrA[0][0] = saddr(Ah) + arow * 48 + aoff;
        adrA[0][1] = adrA[0][0] + 16 * 48;
        adrA[1][0] = saddr(Al) + arow * 48 + aoff;
        adrA[1][1] = adrA[1][0] + 16 * 48;
        int brow = (quad >> 1) * 8 + r8;
        int boff = (quad & 1) * 16;
        #pragma unroll
        for (int j = 0; j < 4; j++) {
            adrB[0][j] = saddr(Bh) + (warp_n * 64 + j * 16 + brow) * 48 + boff;
            adrB[1][j] = saddr(Bl) + (warp_n * 64 + j * 16 + brow) * 48 + boff;
        }
    }

    float acc[2][8][4];
    #pragma unroll
    for (int mf = 0; mf < 2; mf++)
        #pragma unroll
        for (int nf = 0; nf < 8; nf++)
            #pragma unroll
            for (int r = 0; r < 4; r++) acc[mf][nf][r] = 0.f;

    for (int k0 = 0; k0 < K; k0 += 16) {
        // stage A 128x16 (row copy + split)
        {
            int row = tid >> 1, kg = (tid & 1) * 8;
            const float* ap = &A[(size_t)(m0 + row) * K + k0 + kg];
            float4 v0 = *(const float4*)ap;
            float4 v1 = *(const float4*)(ap + 4);
            float l0, l1, l2, l3, l4, l5, l6, l7;
            uint4 h = make_uint4(pack2bf(v0.x, v0.y, l0, l1), pack2bf(v0.z, v0.w, l2, l3),
                                 pack2bf(v1.x, v1.y, l4, l5), pack2bf(v1.z, v1.w, l6, l7));
            *(uint4*)&Ah[row * LDSW + (kg >> 1)] = h;
            *(uint4*)&Al[row * LDSW + (kg >> 1)] =
                make_uint4(pack2bf_o(l0, l1), pack2bf_o(l2, l3),
                           pack2bf_o(l4, l5), pack2bf_o(l6, l7));
        }
        // stage B 16x128 (vertical pairs, transpose into [n][kpair])
        {
            int kp = tid >> 5, ng = (tid & 31) * 4;
            const float* bp = &Bm[(size_t)(k0 + 2 * kp) * N + n0 + ng];
            float4 r0 = *(const float4*)bp;
            float4 r1 = *(const float4*)(bp + N);
            float a0, a1;
            unsigned h;
            h = pack2bf(r0.x, r1.x, a0, a1); Bh[(ng+0)*LDSW + kp] = h; Bl[(ng+0)*LDSW + kp] = pack2bf_o(a0, a1);
            h = pack2bf(r0.y, r1.y, a0, a1); Bh[(ng+1)*LDSW + kp] = h; Bl[(ng+1)*LDSW + kp] = pack2bf_o(a0, a1);
            h = pack2bf(r0.z, r1.z, a0, a1); Bh[(ng+2)*LDSW + kp] = h; Bl[(ng+2)*LDSW + kp] = pack2bf_o(a0, a1);
            h = pack2bf(r0.w, r1.w, a0, a1); Bh[(ng+3)*LDSW + kp] = h; Bl[(ng+3)*LDSW + kp] = pack2bf_o(a0, a1);
        }
        __syncthreads();

        unsigned afh[2][4], afl[2][4];
        ldsm_x4(afh[0], adrA[0][0]); ldsm_x4(afh[1], adrA[0][1]);
        ldsm_x4(afl[0], adrA[1][0]); ldsm_x4(afl[1], adrA[1][1]);
        #pragma unroll
        for (int j = 0; j < 4; j++) {
            unsigned bh[4], bl[4];
            ldsm_x4(bh, adrB[0][j]);
            ldsm_x4(bl, adrB[1][j]);
            #pragma unroll
            for (int mf = 0; mf < 2; mf++) {
                mma_bf16(acc[mf][2*j],   afh[mf], bh[0], bh[1]);
                mma_bf16(acc[mf][2*j],   afh[mf], bl[0], bl[1]);
                mma_bf16(acc[mf][2*j],   afl[mf], bh[0], bh[1]);
                mma_bf16(acc[mf][2*j+1], afh[mf], bh[2], bh[3]);
                mma_bf16(acc[mf][2*j+1], afh[mf], bl[2], bl[3]);
                mma_bf16(acc[mf][2*j+1], afl[mf], bh[2], bh[3]);
            }
        }
        __syncthreads();
    }

    #pragma unroll
    for (int mf = 0; mf < 2; mf++) {
        int row0 = m0 + warp_m * 32 + mf * 16 + g;
        #pragma unroll
        for (int nf = 0; nf < 8; nf++) {
            int col = n0 + warp_n * 64 + nf * 8 + 2 * tq;
            *(float2*)&C[(size_t)row0 * N + col] =
                make_float2(acc[mf][nf][0], acc[mf][nf][1]);
            *(float2*)&C[(size_t)(row0 + 8) * N + col] =
                make_float2(acc[mf][nf][2], acc[mf][nf][3]);
        }
    }
}

// ---------------- ksum[bt][h] = sum_a k[b,t,h,a] ----------------
__global__ void ksum_kernel() {
    int idx = blockIdx.x * blockDim.x + threadIdx.x;   // bt*H + h
    if (idx >= BT * HH) return;
    int bt = idx / HH, h = idx % HH;
    const float4* p = reinterpret_cast<const float4*>(&g_k[(size_t)bt * HA + h * AD]);
    float s = 0.f;
    #pragma unroll
    for (int i = 0; i < AD / 4; i++) { float4 v4 = p[i]; s += v4.x + v4.y + v4.z + v4.w; }
    g_ksum[idx] = s;
}

// ---------------- zero dense bias + winner scratch ----------------
__global__ void zero_bs_kernel() {
    int i = blockIdx.x * blockDim.x + threadIdx.x;
    if (i < BB * TT * TT / 4) {
        ((float4*)g_bs)[i] = make_float4(0.f, 0.f, 0.f, 0.f);
        ((int4*)g_winner)[i] = make_int4(-1, -1, -1, -1);
    }
}

// ---------------- decode edge e ----------------
__device__ __forceinline__ bool decode_edge(const int* __restrict__ ab32, int e,
                                            int& et, int& b, int& qi, int& ki) {
    if (g_is64) {
        const long long* ab = (const long long*)ab32;
        et = (int)ab[4 * e + 0]; b  = (int)ab[4 * e + 1];
        qi = (int)ab[4 * e + 2]; ki = (int)ab[4 * e + 3];
    } else {
        et = ab32[4 * e + 0]; b  = ab32[4 * e + 1];
        qi = ab32[4 * e + 2]; ki = ab32[4 * e + 3];
    }
    return !((unsigned)et >= BIASDIM || (unsigned)b >= BB ||
             (unsigned)qi >= TT || (unsigned)ki >= TT);
}

__global__ void scatter_pass1_kernel(const int* __restrict__ ab32) {
    int e = blockIdx.x * blockDim.x + threadIdx.x;
    if (e >= NEDGE) return;
    int et, b, qi, ki;
    if (!decode_edge(ab32, e, et, b, qi, ki)) return;
    atomicMax(&g_winner[((size_t)b * TT + qi) * TT + ki], e);
}

__global__ void scatter_pass2_kernel(const int* __restrict__ ab32) {
    int e = blockIdx.x * blockDim.x + threadIdx.x;
    if (e >= NEDGE) return;
    int et, b, qi, ki;
    if (!decode_edge(ab32, e, et, b, qi, ki)) return;
    size_t slot = ((size_t)b * TT + qi) * TT + ki;
    if (g_winner[slot] == e) g_bs[slot] = g_proj[et];
}

// ---------------- scores BF16 + ldmatrix: alpha = (QK^T + bs*ksum)*0.125 - mask*BIG
__global__ __launch_bounds__(256, 2)
void scores_bf16_kernel(const float* __restrict__ masks) {
    __shared__ unsigned Ah[128 * LDSW], Al[128 * LDSW];   // Q: [q][apair]
    __shared__ unsigned Bh[128 * LDSW], Bl[128 * LDSW];   // K: [ktok][apair]
    __shared__ float ks_s[128];
    const int z = blockIdx.z;                 // b*H + h
    const int b = z >> 4, h = z & 15;
    const int q0 = blockIdx.y * 128, k0c = blockIdx.x * 128;
    const int tid = threadIdx.x;
    const int wid = tid >> 5, lane = tid & 31;
    const int g = lane >> 2, tq = lane & 3;
    const int r8 = lane & 7, quad = lane >> 3;
    const int warp_m = wid >> 1, warp_n = wid & 1;
    const float* qbase = g_q + (size_t)(b * TT + q0)  * HA + h * AD;
    const float* kbase = g_k + (size_t)(b * TT + k0c) * HA + h * AD;
    if (tid < 128) ks_s[tid] = g_ksum[(size_t)(b * TT + k0c + tid) * HH + h];

    unsigned adrA[2][2], adrB[2][4];
    {
        int arow = warp_m * 32 + (quad & 1) * 8 + r8;
        int aoff = (quad >> 1) * 16;
        adrA[0][0] = saddr(Ah) + arow * 48 + aoff;
        adrA[0][1] = adrA[0][0] + 16 * 48;
        adrA[1][0] = saddr(Al) + arow * 48 + aoff;
        adrA[1][1] = adrA[1][0] + 16 * 48;
        int brow = (quad >> 1) * 8 + r8;
        int boff = (quad & 1) * 16;
        #pragma unroll
        for (int j = 0; j < 4; j++) {
            adrB[0][j] = saddr(Bh) + (warp_n * 64 + j * 16 + brow) * 48 + boff;
            adrB[1][j] = saddr(Bl) + (warp_n * 64 + j * 16 + brow) * 48 + boff;
        }
    }

    float acc[2][8][4];
    #pragma unroll
    for (int mf = 0; mf < 2; mf++)
        #pragma unroll
        for (int nf = 0; nf < 8; nf++)
            #pragma unroll
            for (int r = 0; r < 4; r++) acc[mf][nf][r] = 0.f;

    #pragma unroll
    for (int a0 = 0; a0 < AD; a0 += 16) {
        // stage Q and K (row copies + split)
        {
            int row = tid >> 1, kg = (tid & 1) * 8;
            const float* qp = &qbase[(size_t)row * HA + a0 + kg];
            const float* kp = &kbase[(size_t)row * HA + a0 + kg];
            float4 v0 = *(const float4*)qp;
            float4 v1 = *(const float4*)(qp + 4);
            float l0, l1, l2, l3, l4, l5, l6, l7;
            *(uint4*)&Ah[row * LDSW + (kg >> 1)] =
                make_uint4(pack2bf(v0.x, v0.y, l0, l1), pack2bf(v0.z, v0.w, l2, l3),
                           pack2bf(v1.x, v1.y, l4, l5), pack2bf(v1.z, v1.w, l6, l7));
            *(uint4*)&Al[row * LDSW + (kg >> 1)] =
                make_uint4(pack2bf_o(l0, l1), pack2bf_o(l2, l3),
                           pack2bf_o(l4, l5), pack2bf_o(l6, l7));
            float4 w0 = *(const float4*)kp;
            float4 w1 = *(const float4*)(kp + 4);
            *(uint4*)&Bh[row * LDSW + (kg >> 1)] =
                make_uint4(pack2bf(w0.x, w0.y, l0, l1), pack2bf(w0.z, w0.w, l2, l3),
                           pack2bf(w1.x, w1.y, l4, l5), pack2bf(w1.z, w1.w, l6, l7));
            *(uint4*)&Bl[row * LDSW + (kg >> 1)] =
                make_uint4(pack2bf_o(l0, l1), pack2bf_o(l2, l3),
                           pack2bf_o(l4, l5), pack2bf_o(l6, l7));
        }
        __syncthreads();
        unsigned afh[2][4], afl[2][4];
        ldsm_x4(afh[0], adrA[0][0]); ldsm_x4(afh[1], adrA[0][1]);
        ldsm_x4(afl[0], adrA[1][0]); ldsm_x4(afl[1], adrA[1][1]);
        #pragma unroll
        for (int j = 0; j < 4; j++) {
            unsigned bh[4], bl[4];
            ldsm_x4(bh, adrB[0][j]);
            ldsm_x4(bl, adrB[1][j]);
            #pragma unroll
            for (int mf = 0; mf < 2; mf++) {
                mma_bf16(acc[mf][2*j],   afh[mf], bh[0], bh[1]);
                mma_bf16(acc[mf][2*j],   afh[mf], bl[0], bl[1]);
                mma_bf16(acc[mf][2*j],   afl[mf], bh[0], bh[1]);
                mma_bf16(acc[mf][2*j+1], afh[mf], bh[2], bh[3]);
                mma_bf16(acc[mf][2*j+1], afh[mf], bl[2], bl[3]);
                mma_bf16(acc[mf][2*j+1], afl[mf], bh[2], bh[3]);
            }
        }
        __syncthreads();
    }

    #pragma unroll
    for (int mf = 0; mf < 2; mf++) {
        int row0 = q0 + warp_m * 32 + mf * 16 + g;
        #pragma unroll
        for (int nf = 0; nf < 8; nf++) {
            int lc  = warp_n * 64 + nf * 8 + 2 * tq;
            int col = k0c + lc;
            float ka = ks_s[lc], kb = ks_s[lc + 1];
            #pragma unroll
            for (int r = 0; r < 2; r++) {
                int qi = row0 + r * 8;
                size_t rowbm = ((size_t)b * TT + qi) * TT + col;
                float2 bs2 = *(const float2*)&g_bs[rowbm];
                float2 mk2 = *(const float2*)&masks[rowbm];
                float v0 = (acc[mf][nf][2 * r]     + bs2.x * ka) * 0.125f - mk2.x * FBIG;
                float v1 = (acc[mf][nf][2 * r + 1] + bs2.y * kb) * 0.125f - mk2.y * FBIG;
                *(float2*)&g_alpha[((size_t)z * TT + qi) * TT + col] = make_float2(v0, v1);
            }
        }
    }
}

// ---------------- rowstat: per row, (max, 1/sum(exp(x-max))) -------------------
__global__ void rowstat_kernel() {
    __shared__ float smax[8];
    __shared__ float ssum[8];
    const float4* p = (const float4*)(g_alpha + (size_t)blockIdx.x * TT);
    const int tid = threadIdx.x;                 // 256
    const int lane = tid & 31, wid = tid >> 5;
    float4 x = p[tid];
    float mx = fmaxf(fmaxf(x.x, x.y), fmaxf(x.z, x.w));
    #pragma unroll
    for (int o = 16; o; o >>= 1) mx = fmaxf(mx, __shfl_xor_sync(0xffffffffu, mx, o));
    if (lane == 0) smax[wid] = mx;
    __syncthreads();
    mx = smax[0];
    #pragma unroll
    for (int w = 1; w < 8; w++) mx = fmaxf(mx, smax[w]);
    float s = fexp(x.x - mx) + fexp(x.y - mx) + fexp(x.z - mx) + fexp(x.w - mx);
    #pragma unroll
    for (int o = 16; o; o >>= 1) s += __shfl_xor_sync(0xffffffffu, s, o);
    if (lane == 0) ssum[wid] = s;
    __syncthreads();
    if (tid == 0) {
        float tot = 0.f;
        #pragma unroll
        for (int w = 0; w < 8; w++) tot += ssum[w];
        g_rowstat[blockIdx.x] = make_float2(mx, 1.0f / tot);
    }
}

// ---------------- context BF16 + ldmatrix + fused softmax normalize ------------
__global__ __launch_bounds__(256, 2)
void context_bf16_kernel() {
    __shared__ unsigned Ah[128 * LDSW], Al[128 * LDSW];   // P: [q][kpair]
    __shared__ unsigned Bh[64 * LDSW],  Bl[64 * LDSW];    // V: [a][kpair]
    __shared__ float2 rs_s[128];
    const int z = blockIdx.y;                 // b*H + h
    const int b = z >> 4, h = z & 15;
    const int q0 = blockIdx.x * 128;
    const int tid = threadIdx.x;
    const int wid = tid >> 5, lane = tid & 31;
    const int g = lane >> 2, tq = lane & 3;
    const int r8 = lane & 7, quad = lane >> 3;
    const int warp_m = wid >> 1, warp_n = wid & 1;
    const float* arow  = g_alpha + ((size_t)z * TT + q0) * TT;
    const float* vbase = g_v + (size_t)(b * TT) * HA + h * AD;
    if (tid < 128) rs_s[tid] = g_rowstat[(size_t)z * TT + q0 + tid];

    unsigned adrA[2][2], adrB[2][2];
    {
        int arw = warp_m * 32 + (quad & 1) * 8 + r8;
        int aoff = (quad >> 1) * 16;
        adrA[0][0] = saddr(Ah) + arw * 48 + aoff;
        adrA[0][1] = adrA[0][0] + 16 * 48;
        adrA[1][0] = saddr(Al) + arw * 48 + aoff;
        adrA[1][1] = adrA[1][0] + 16 * 48;
        int brow = (quad >> 1) * 8 + r8;
        int boff = (quad & 1) * 16;
        #pragma unroll
        for (int j = 0; j < 2; j++) {
            adrB[0][j] = saddr(Bh) + (warp_n * 32 + j * 16 + brow) * 48 + boff;
            adrB[1][j] = saddr(Bl) + (warp_n * 32 + j * 16 + brow) * 48 + boff;
        }
    }
    __syncthreads();

    float acc[2][4][4];
    #pragma unroll
    for (int mf = 0; mf < 2; mf++)
        #pragma unroll
        for (int nf = 0; nf < 4; nf++)
            #pragma unroll
            for (int r = 0; r < 4; r++) acc[mf][nf][r] = 0.f;

    for (int k0 = 0; k0 < TT; k0 += 16) {
        // stage P 128x16 : p = exp(alpha - mx)
        {
            int row = tid >> 1, kg = (tid & 1) * 8;
            float mx = rs_s[row].x;
            const float* ap = &arow[(size_t)row * TT + k0 + kg];
            float4 v0 = *(const float4*)ap;
            float4 v1 = *(const float4*)(ap + 4);
            float p0 = fexp(v0.x - mx), p1 = fexp(v0.y - mx);
            float p2 = fexp(v0.z - mx), p3 = fexp(v0.w - mx);
            float p4 = fexp(v1.x - mx), p5 = fexp(v1.y - mx);
            float p6 = fexp(v1.z - mx), p7 = fexp(v1.w - mx);
            float l0, l1, l2, l3, l4, l5, l6, l7;
            *(uint4*)&Ah[row * LDSW + (kg >> 1)] =
                make_uint4(pack2bf(p0, p1, l0, l1), pack2bf(p2, p3, l2, l3),
                           pack2bf(p4, p5, l4, l5), pack2bf(p6, p7, l6, l7));
            *(uint4*)&Al[row * LDSW + (kg >> 1)] =
                make_uint4(pack2bf_o(l0, l1), pack2bf_o(l2, l3),
                           pack2bf_o(l4, l5), pack2bf_o(l6, l7));
        }
        // stage V 16x64 (vertical pairs into [a][kpair])
        {
            int kp = tid >> 5, ag = (tid & 31) * 2;
            const float* vp = &vbase[(size_t)(k0 + 2 * kp) * HA + ag];
            float2 r0 = *(const float2*)vp;
            float2 r1 = *(const float2*)(vp + HA);
            float a0, a1;
            unsigned hh;
            hh = pack2bf(r0.x, r1.x, a0, a1);
            Bh[(ag+0)*LDSW + kp] = hh; Bl[(ag+0)*LDSW + kp] = pack2bf_o(a0, a1);
            hh = pack2bf(r0.y, r1.y, a0, a1);
            Bh[(ag+1)*LDSW + kp] = hh; Bl[(ag+1)*LDSW + kp] = pack2bf_o(a0, a1);
        }
        __syncthreads();
        unsigned afh[2][4], afl[2][4];
        ldsm_x4(afh[0], adrA[0][0]); ldsm_x4(afh[1], adrA[0][1]);
        ldsm_x4(afl[0], adrA[1][0]); ldsm_x4(afl[1], adrA[1][1]);
        #pragma unroll
        for (int j = 0; j < 2; j++) {
            unsigned bh[4], bl[4];
            ldsm_x4(bh, adrB[0][j]);
            ldsm_x4(bl, adrB[1][j]);
            #pragma unroll
            for (int mf = 0; mf < 2; mf++) {
                mma_bf16(acc[mf][2*j],   afh[mf], bh[0], bh[1]);
                mma_bf16(acc[mf][2*j],   afh[mf], bl[0], bl[1]);
                mma_bf16(acc[mf][2*j],   afl[mf], bh[0], bh[1]);
                mma_bf16(acc[mf][2*j+1], afh[mf], bh[2], bh[3]);
                mma_bf16(acc[mf][2*j+1], afh[mf], bl[2], bl[3]);
                mma_bf16(acc[mf][2*j+1], afl[mf], bh[2], bh[3]);
            }
        }
        __syncthreads();
    }

    #pragma unroll
    for (int mf = 0; mf < 2; mf++) {
        int lr0 = warp_m * 32 + mf * 16 + g;
        float inv0 = rs_s[lr0].y, inv1 = rs_s[lr0 + 8].y;
        int row0 = q0 + lr0;
        #pragma unroll
        for (int nf = 0; nf < 4; nf++) {
            int col = warp_n * 32 + nf * 8 + 2 * tq;
            *(float2*)&g_ctx[(size_t)(b * TT + row0) * HA + h * AD + col] =
                make_float2(acc[mf][nf][0] * inv0, acc[mf][nf][1] * inv0);
            *(float2*)&g_ctx[(size_t)(b * TT + row0 + 8) * HA + h * AD + col] =
                make_float2(acc[mf][nf][2] * inv1, acc[mf][nf][3] * inv1);
        }
    }
}

// ---------------- launch ----------------
extern "C" void kernel_launch(void* const* d_in, const int* in_sizes, int n_in,
                              void* d_out, int out_size) {
    const float* states     = (const float*)d_in[0];
    const float* key_states = (const float*)d_in[1];
    const float* masks      = (const float*)d_in[2];
    const int*   ab32       = (const int*)d_in[3];
    const float* Wq         = (const float*)d_in[4];
    const float* Wk         = (const float*)d_in[5];
    const float* Wv         = (const float*)d_in[6];
    const float* Wout       = (const float*)d_in[7];
    const float* embs       = (const float*)d_in[8];
    const float* scal       = (const float*)d_in[9];
    float* out              = (float*)d_out;

    dim3 gemm_grid(HA / 128, BT / 128);   // (8, 64)

    // QKV projections — bf16 tensor cores (3-term split, ldmatrix)
    bf16_gemm_kernel<<<gemm_grid, 256>>>(states,     Wq, nullptr, 0, 0, BT, HA, DD);
    bf16_gemm_kernel<<<gemm_grid, 256>>>(key_states, Wk, nullptr, 0, 1, BT, HA, DD);
    bf16_gemm_kernel<<<gemm_grid, 256>>>(key_states, Wv, nullptr, 0, 2, BT, HA, DD);

    // ksum
    ksum_kernel<<<(BT * HH + 255) / 256, 256>>>();

    // edge-bias detect + projection + deterministic scatter
    detect_kernel<<<1, 1>>>(ab32);
    proj_kernel<<<1, 32>>>(embs, scal);
    zero_bs_kernel<<<(BB * TT * TT / 4 + 255) / 256, 256>>>();
    scatter_pass1_kernel<<<(NEDGE + 255) / 256, 256>>>(ab32);
    scatter_pass2_kernel<<<(NEDGE + 255) / 256, 256>>>(ab32);

    // scores (bf16 + ldmatrix) + row stats
    dim3 sc_grid(TT / 128, TT / 128, BB * HH);   // (8, 8, 128)
    scores_bf16_kernel<<<sc_grid, 256>>>(masks);
    rowstat_kernel<<<BB * HH * TT, 256>>>();

    // context (bf16 + ldmatrix, fused exp-normalize)
    dim3 cx_grid(TT / 128, BB * HH);             // (8, 128)
    context_bf16_kernel<<<cx_grid, 256>>>();

    // output projection
    bf16_gemm_kernel<<<gemm_grid, 256>>>(nullptr, Wout, out, 1, 3, BT, DD, HA);
}